// round 10
// baseline (speedup 1.0000x reference)
#include <cuda_runtime.h>
#include <cuda_bf16.h>
#include <cstdint>

// Problem constants
#define BATCH 2
#define SEQ   2048
#define DIN   1024
#define DOUT  1024
#define NHEAD 16
#define HDIM  64
#define M_ROWS (BATCH * SEQ)          // 4096
#define QKV_COLS (3 * DOUT)           // 3072

// Scratch (device globals; no runtime allocation allowed)
__device__ float g_qkv[(size_t)M_ROWS * QKV_COLS];   // tf32-rounded, Q pre-scaled
__device__ float g_y[(size_t)M_ROWS * DOUT];         // tf32-rounded

// ---------------------------------------------------------------------------
// PTX helpers
// ---------------------------------------------------------------------------
__device__ __forceinline__ void cp_async16(void* smem, const void* gmem) {
    uint32_t s = (uint32_t)__cvta_generic_to_shared(smem);
    asm volatile("cp.async.cg.shared.global [%0], [%1], 16;\n" :: "r"(s), "l"(gmem));
}
__device__ __forceinline__ void cp_commit() {
    asm volatile("cp.async.commit_group;\n");
}
template <int N>
__device__ __forceinline__ void cp_wait() {
    asm volatile("cp.async.wait_group %0;\n" :: "n"(N));
}
__device__ __forceinline__ uint32_t f2tf(float f) {
    uint32_t r;
    asm("cvt.rna.tf32.f32 %0, %1;" : "=r"(r) : "f"(f));
    return r;
}
__device__ __forceinline__ float tf32r(float f) {
    return __uint_as_float(f2tf(f));
}
__device__ __forceinline__ void mma_tf32(float c[4],
                                         const uint32_t a[4],
                                         const uint32_t b[2]) {
    asm volatile(
        "mma.sync.aligned.m16n8k8.row.col.f32.tf32.tf32.f32 "
        "{%0,%1,%2,%3}, {%4,%5,%6,%7}, {%8,%9}, {%0,%1,%2,%3};\n"
        : "+f"(c[0]), "+f"(c[1]), "+f"(c[2]), "+f"(c[3])
        : "r"(a[0]), "r"(a[1]), "r"(a[2]), "r"(a[3]), "r"(b[0]), "r"(b[1]));
}

// ---------------------------------------------------------------------------
// TF32 tensor-core GEMM: C[M,N] = A[M,K] @ B[N,K]^T (+bias)
// R7 structure exactly, but 4-stage cp.async pipeline (3 loads in flight),
// one __syncthreads per K-stage. BK=16, stride 20, conflict-free frag LDS.
// ---------------------------------------------------------------------------
#define BM 128
#define BN 128
#define BK 16
#define GST 20                       // BK + 4 pad
#define STAGE_FLOATS (2 * BM * GST)  // 5120 floats
#define NSTAGE 4
#define GEMM_SMEM_BYTES (NSTAGE * STAGE_FLOATS * 4)   // 81920 B

template <bool BIAS, bool ROUND, bool QSCALE>
__global__ __launch_bounds__(256, 2) void gemm_tf32_nt(
    const float* __restrict__ A, const float* __restrict__ B,
    const float* __restrict__ bias, float* __restrict__ C,
    int M, int N, int K)
{
    extern __shared__ float sm[];

    const int tid  = threadIdx.x;
    const int lane = tid & 31;
    const int warp = tid >> 5;
    const int wm = warp & 1;          // 2 warps along M (64 rows each)
    const int wn = warp >> 1;         // 4 warps along N (32 cols each)
    const int g  = lane >> 2;
    const int tg = lane & 3;

    const int bm = blockIdx.y * BM;
    const int bn = blockIdx.x * BN;

    const int ldr = tid >> 2;          // 0..63
    const int ldc = (tid & 3) * 4;     // 0,4,8,12

    const float* Ag0 = A + (size_t)(bm + ldr) * K + ldc;
    const float* Ag1 = A + (size_t)(bm + ldr + 64) * K + ldc;
    const float* Bg0 = B + (size_t)(bn + ldr) * K + ldc;
    const float* Bg1 = B + (size_t)(bn + ldr + 64) * K + ldc;

    auto load_stage = [&](int s, int ko) {
        float* As = sm + s * STAGE_FLOATS;
        float* Bs = As + BM * GST;
        cp_async16(As + ldr * GST + ldc,        Ag0 + ko);
        cp_async16(As + (ldr + 64) * GST + ldc, Ag1 + ko);
        cp_async16(Bs + ldr * GST + ldc,        Bg0 + ko);
        cp_async16(Bs + (ldr + 64) * GST + ldc, Bg1 + ko);
        cp_commit();
    };

    float acc[4][4][4];
#pragma unroll
    for (int mt = 0; mt < 4; mt++)
#pragma unroll
        for (int nt = 0; nt < 4; nt++)
#pragma unroll
            for (int i = 0; i < 4; i++) acc[mt][nt][i] = 0.f;

    const int nstages = K / BK;

    // prologue: stages 0,1,2 in flight
    load_stage(0, 0);
    load_stage(1, BK);
    load_stage(2, 2 * BK);

    for (int it = 0; it < nstages; it++) {
        const int rem = nstages - 1 - it;
        if (rem >= 2)      cp_wait<2>();
        else if (rem == 1) cp_wait<1>();
        else               cp_wait<0>();
        __syncthreads();   // stage `it` visible; all warps done with it-1

        if (it + 3 < nstages)
            load_stage((it + 3) % NSTAGE, (it + 3) * BK);

        const float* Ab = sm + (it % NSTAGE) * STAGE_FLOATS;
        const float* Bb = Ab + BM * GST;

#pragma unroll
        for (int ks = 0; ks < BK; ks += 8) {
            uint32_t af[4][4], bf[4][2];
#pragma unroll
            for (int mt = 0; mt < 4; mt++) {
                const int m = wm * 64 + mt * 16;
                af[mt][0] = f2tf(Ab[(m + g) * GST + ks + tg]);
                af[mt][1] = f2tf(Ab[(m + g + 8) * GST + ks + tg]);
                af[mt][2] = f2tf(Ab[(m + g) * GST + ks + tg + 4]);
                af[mt][3] = f2tf(Ab[(m + g + 8) * GST + ks + tg + 4]);
            }
#pragma unroll
            for (int nt = 0; nt < 4; nt++) {
                const int n = wn * 32 + nt * 8;
                bf[nt][0] = f2tf(Bb[(n + g) * GST + ks + tg]);
                bf[nt][1] = f2tf(Bb[(n + g) * GST + ks + tg + 4]);
            }
#pragma unroll
            for (int mt = 0; mt < 4; mt++)
#pragma unroll
                for (int nt = 0; nt < 4; nt++)
                    mma_tf32(acc[mt][nt], af[mt], bf[nt]);
        }
    }

    const float qsc = 0.125f * 1.4426950408889634f;

#pragma unroll
    for (int mt = 0; mt < 4; mt++) {
        const int row0 = bm + wm * 64 + mt * 16 + g;
#pragma unroll
        for (int nt = 0; nt < 4; nt++) {
            const int col = bn + wn * 32 + nt * 8 + 2 * tg;
            float v0 = acc[mt][nt][0], v1 = acc[mt][nt][1];
            float v2 = acc[mt][nt][2], v3 = acc[mt][nt][3];
            if (QSCALE && col < DOUT) { v0 *= qsc; v1 *= qsc; v2 *= qsc; v3 *= qsc; }
            if (BIAS) {
                float b0 = bias[col], b1 = bias[col + 1];
                v0 += b0; v1 += b1; v2 += b0; v3 += b1;
            }
            if (ROUND) {
                v0 = tf32r(v0); v1 = tf32r(v1);
                v2 = tf32r(v2); v3 = tf32r(v3);
            }
            *(float2*)(C + (size_t)row0 * N + col) = make_float2(v0, v1);
            *(float2*)(C + (size_t)(row0 + 8) * N + col) = make_float2(v2, v3);
        }
    }
}

// ---------------------------------------------------------------------------
// Flash attention (causal), tf32 mma — exact R7 configuration (1 CTA/SM).
// ---------------------------------------------------------------------------
#define KS_ST 68
#define VS_ST 72
#define FLASH_SMEM_BYTES ((2*64*KS_ST + 2*64*VS_ST + 128*KS_ST) * 4)

__global__ __launch_bounds__(256, 1) void flash_mma_kernel(
    const float* __restrict__ qkv, float* __restrict__ y)
{
    extern __shared__ float sm[];
    float (*Ks)[64][KS_ST] = (float(*)[64][KS_ST])sm;
    float (*Vs)[64][VS_ST] = (float(*)[64][VS_ST])(sm + 2 * 64 * KS_ST);
    float (*Ps)[KS_ST]     = (float(*)[KS_ST])(sm + 2 * 64 * KS_ST + 2 * 64 * VS_ST);

    const int qi = (int)gridDim.x - 1 - (int)blockIdx.x;  // heavy tiles first
    const int bh = blockIdx.y;
    const int b  = bh >> 4;
    const int h  = bh & 15;
    const int qbase = qi * 128;

    const float* base = qkv + (size_t)b * SEQ * QKV_COLS;
    const int hoff = h * HDIM;

    const int tid  = threadIdx.x;
    const int lane = tid & 31;
    const int warp = tid >> 5;
    const int g  = lane >> 2;
    const int tg = lane & 3;
    const int w16 = warp * 16;

    for (int i = tid; i < 128 * 16; i += 256) {
        int r  = i >> 4;
        int c4 = (i & 15) * 4;
        float4 v = *(const float4*)(base + (size_t)(qbase + r) * QKV_COLS + hoff + c4);
        *(float4*)&Ps[r][c4] = v;
    }
    __syncthreads();

    uint32_t aq[8][4];
#pragma unroll
    for (int ks = 0; ks < 8; ks++) {
        aq[ks][0] = __float_as_uint(Ps[w16 + g][ks * 8 + tg]);
        aq[ks][1] = __float_as_uint(Ps[w16 + g + 8][ks * 8 + tg]);
        aq[ks][2] = __float_as_uint(Ps[w16 + g][ks * 8 + tg + 4]);
        aq[ks][3] = __float_as_uint(Ps[w16 + g + 8][ks * 8 + tg + 4]);
    }
    __syncthreads();

    float O[8][4];
#pragma unroll
    for (int n = 0; n < 8; n++)
#pragma unroll
        for (int i = 0; i < 4; i++) O[n][i] = 0.f;
    float m0 = -1e30f, m1 = -1e30f, l0 = 0.f, l1 = 0.f;

    const int njt = 2 * (qi + 1);

    auto prefetch = [&](int jt, int buf) {
        const int jb = jt * 64;
        for (int i = tid; i < 64 * 16; i += 256) {
            int r  = i >> 4;
            int c4 = (i & 15) * 4;
            const float* rowp = base + (size_t)(jb + r) * QKV_COLS + hoff;
            cp_async16(&Ks[buf][r][c4], rowp + DOUT + c4);
            cp_async16(&Vs[buf][r][c4], rowp + 2 * DOUT + c4);
        }
        cp_commit();
    };

    prefetch(0, 0);

    for (int jt = 0; jt < njt; jt++) {
        const int buf = jt & 1;
        if (jt + 1 < njt) {
            prefetch(jt + 1, (jt + 1) & 1);
            cp_wait<1>();
        } else {
            cp_wait<0>();
        }
        __syncthreads();

        float S[8][4];
#pragma unroll
        for (int n = 0; n < 8; n++)
#pragma unroll
            for (int i = 0; i < 4; i++) S[n][i] = 0.f;

#pragma unroll
        for (int ks = 0; ks < 8; ks++) {
#pragma unroll
            for (int n = 0; n < 8; n++) {
                uint32_t kb[2];
                kb[0] = __float_as_uint(Ks[buf][n * 8 + g][ks * 8 + tg]);
                kb[1] = __float_as_uint(Ks[buf][n * 8 + g][ks * 8 + tg + 4]);
                mma_tf32(S[n], aq[ks], kb);
            }
        }

        if (jt >= 2 * qi) {
            const int r0 = qbase + w16 + g;
            const int r1 = r0 + 8;
            const int cb = jt * 64 + 2 * tg;
#pragma unroll
            for (int n = 0; n < 8; n++) {
                const int c0 = cb + n * 8;
                if (c0 > r0)     S[n][0] = -1e30f;
                if (c0 + 1 > r0) S[n][1] = -1e30f;
                if (c0 > r1)     S[n][2] = -1e30f;
                if (c0 + 1 > r1) S[n][3] = -1e30f;
            }
        }

        float rm0 = -1e30f, rm1 = -1e30f;
#pragma unroll
        for (int n = 0; n < 8; n++) {
            rm0 = fmaxf(rm0, fmaxf(S[n][0], S[n][1]));
            rm1 = fmaxf(rm1, fmaxf(S[n][2], S[n][3]));
        }
        rm0 = fmaxf(rm0, __shfl_xor_sync(0xffffffffu, rm0, 1));
        rm0 = fmaxf(rm0, __shfl_xor_sync(0xffffffffu, rm0, 2));
        rm1 = fmaxf(rm1, __shfl_xor_sync(0xffffffffu, rm1, 1));
        rm1 = fmaxf(rm1, __shfl_xor_sync(0xffffffffu, rm1, 2));

        const float mn0 = fmaxf(m0, rm0);
        const float mn1 = fmaxf(m1, rm1);
        const float corr0 = exp2f(m0 - mn0);
        const float corr1 = exp2f(m1 - mn1);
        m0 = mn0; m1 = mn1;

        float rs0 = 0.f, rs1 = 0.f;
#pragma unroll
        for (int n = 0; n < 8; n++) {
            float p0 = exp2f(S[n][0] - mn0);
            float p1 = exp2f(S[n][1] - mn0);
            float p2 = exp2f(S[n][2] - mn1);
            float p3 = exp2f(S[n][3] - mn1);
            rs0 += p0 + p1;
            rs1 += p2 + p3;
            O[n][0] *= corr0; O[n][1] *= corr0;
            O[n][2] *= corr1; O[n][3] *= corr1;
            *(float2*)&Ps[w16 + g][n * 8 + 2 * tg]     = make_float2(tf32r(p0), tf32r(p1));
            *(float2*)&Ps[w16 + g + 8][n * 8 + 2 * tg] = make_float2(tf32r(p2), tf32r(p3));
        }
        rs0 += __shfl_xor_sync(0xffffffffu, rs0, 1);
        rs0 += __shfl_xor_sync(0xffffffffu, rs0, 2);
        rs1 += __shfl_xor_sync(0xffffffffu, rs1, 1);
        rs1 += __shfl_xor_sync(0xffffffffu, rs1, 2);
        l0 = l0 * corr0 + rs0;
        l1 = l1 * corr1 + rs1;

        __syncwarp();

#pragma unroll
        for (int ks = 0; ks < 8; ks++) {
            uint32_t pa[4];
            pa[0] = __float_as_uint(Ps[w16 + g][ks * 8 + tg]);
            pa[1] = __float_as_uint(Ps[w16 + g + 8][ks * 8 + tg]);
            pa[2] = __float_as_uint(Ps[w16 + g][ks * 8 + tg + 4]);
            pa[3] = __float_as_uint(Ps[w16 + g + 8][ks * 8 + tg + 4]);
#pragma unroll
            for (int n = 0; n < 8; n++) {
                uint32_t vb[2];
                vb[0] = __float_as_uint(Vs[buf][ks * 8 + tg][n * 8 + g]);
                vb[1] = __float_as_uint(Vs[buf][ks * 8 + tg + 4][n * 8 + g]);
                mma_tf32(O[n], pa, vb);
            }
        }
        __syncthreads();
    }

    const float inv0 = 1.0f / l0;
    const float inv1 = 1.0f / l1;
    const int r0 = qbase + w16 + g;
    float* yr0 = y + (size_t)b * SEQ * DOUT + (size_t)r0 * DOUT + hoff;
    float* yr1 = yr0 + 8 * DOUT;
#pragma unroll
    for (int n = 0; n < 8; n++) {
        const int c = n * 8 + 2 * tg;
        *(float2*)(yr0 + c) = make_float2(tf32r(O[n][0] * inv0), tf32r(O[n][1] * inv0));
        *(float2*)(yr1 + c) = make_float2(tf32r(O[n][2] * inv1), tf32r(O[n][3] * inv1));
    }
}

// ---------------------------------------------------------------------------
extern "C" void kernel_launch(void* const* d_in, const int* in_sizes, int n_in,
                              void* d_out, int out_size)
{
    const float* x     = (const float*)d_in[0];
    const float* w_qkv = (const float*)d_in[1];
    const float* w_out = (const float*)d_in[2];
    const float* b_out = (const float*)d_in[3];
    float* out = (float*)d_out;

    float *qkv_ptr, *y_ptr;
    cudaGetSymbolAddress((void**)&qkv_ptr, g_qkv);
    cudaGetSymbolAddress((void**)&y_ptr, g_y);

    cudaFuncSetAttribute(gemm_tf32_nt<false, true, true>,
                         cudaFuncAttributeMaxDynamicSharedMemorySize,
                         GEMM_SMEM_BYTES);
    cudaFuncSetAttribute(gemm_tf32_nt<true, false, false>,
                         cudaFuncAttributeMaxDynamicSharedMemorySize,
                         GEMM_SMEM_BYTES);
    cudaFuncSetAttribute(flash_mma_kernel,
                         cudaFuncAttributeMaxDynamicSharedMemorySize,
                         FLASH_SMEM_BYTES);

    // 1) QKV projection (output tf32-rounded, Q pre-scaled by 0.125*log2e)
    gemm_tf32_nt<false, true, true>
        <<<dim3(QKV_COLS / BN, M_ROWS / BM), 256, GEMM_SMEM_BYTES>>>(
        x, w_qkv, nullptr, qkv_ptr, M_ROWS, QKV_COLS, DIN);

    // 2) Flash attention (y stored tf32-rounded)
    flash_mma_kernel<<<dim3(SEQ / 128, BATCH * NHEAD), 256, FLASH_SMEM_BYTES>>>(
        qkv_ptr, y_ptr);

    // 3) Output projection + bias (final fp32 output)
    gemm_tf32_nt<true, false, false>
        <<<dim3(DOUT / BN, M_ROWS / BM), 256, GEMM_SMEM_BYTES>>>(
        y_ptr, w_out, b_out, out, M_ROWS, DOUT, DOUT);
}

// round 11
// speedup vs baseline: 1.0995x; 1.0995x over previous
#include <cuda_runtime.h>
#include <cuda_bf16.h>
#include <cstdint>

// Problem constants
#define BATCH 2
#define SEQ   2048
#define DIN   1024
#define DOUT  1024
#define NHEAD 16
#define HDIM  64
#define M_ROWS (BATCH * SEQ)          // 4096
#define QKV_COLS (3 * DOUT)           // 3072

// Scratch (device globals; no runtime allocation allowed)
__device__ float g_qkv[(size_t)M_ROWS * QKV_COLS];   // tf32-rounded, Q pre-scaled
__device__ float g_y[(size_t)M_ROWS * DOUT];         // tf32-rounded

// ---------------------------------------------------------------------------
// PTX helpers
// ---------------------------------------------------------------------------
__device__ __forceinline__ void cp_async16(void* smem, const void* gmem) {
    uint32_t s = (uint32_t)__cvta_generic_to_shared(smem);
    asm volatile("cp.async.cg.shared.global [%0], [%1], 16;\n" :: "r"(s), "l"(gmem));
}
__device__ __forceinline__ void cp_commit() {
    asm volatile("cp.async.commit_group;\n");
}
template <int N>
__device__ __forceinline__ void cp_wait() {
    asm volatile("cp.async.wait_group %0;\n" :: "n"(N));
}
__device__ __forceinline__ uint32_t f2tf(float f) {
    uint32_t r;
    asm("cvt.rna.tf32.f32 %0, %1;" : "=r"(r) : "f"(f));
    return r;
}
__device__ __forceinline__ float tf32r(float f) {
    return __uint_as_float(f2tf(f));
}
// Guaranteed single MUFU EX2 regardless of -use_fast_math
__device__ __forceinline__ float ex2(float x) {
    float y;
    asm("ex2.approx.f32 %0, %1;" : "=f"(y) : "f"(x));
    return y;
}
__device__ __forceinline__ float rcp(float x) {
    float y;
    asm("rcp.approx.f32 %0, %1;" : "=f"(y) : "f"(x));
    return y;
}
__device__ __forceinline__ void mma_tf32(float c[4],
                                         const uint32_t a[4],
                                         const uint32_t b[2]) {
    asm volatile(
        "mma.sync.aligned.m16n8k8.row.col.f32.tf32.tf32.f32 "
        "{%0,%1,%2,%3}, {%4,%5,%6,%7}, {%8,%9}, {%0,%1,%2,%3};\n"
        : "+f"(c[0]), "+f"(c[1]), "+f"(c[2]), "+f"(c[3])
        : "r"(a[0]), "r"(a[1]), "r"(a[2]), "r"(a[3]), "r"(b[0]), "r"(b[1]));
}

// ---------------------------------------------------------------------------
// TF32 tensor-core GEMM: C[M,N] = A[M,K] @ B[N,K]^T (+bias)
// R7 EXACT: 3-stage cp.async pipeline, one __syncthreads per K-stage,
// BK=16, stride 20, in-loop cvt.rna fragment loads (measured best: 197.6us).
// ---------------------------------------------------------------------------
#define BM 128
#define BN 128
#define BK 16
#define GST 20                       // BK + 4 pad
#define STAGE_FLOATS (2 * BM * GST)  // 5120 floats
#define NSTAGE 3
#define GEMM_SMEM_BYTES (NSTAGE * STAGE_FLOATS * 4)   // 61440 B

template <bool BIAS, bool ROUND, bool QSCALE>
__global__ __launch_bounds__(256, 2) void gemm_tf32_nt(
    const float* __restrict__ A, const float* __restrict__ B,
    const float* __restrict__ bias, float* __restrict__ C,
    int M, int N, int K)
{
    extern __shared__ float sm[];

    const int tid  = threadIdx.x;
    const int lane = tid & 31;
    const int warp = tid >> 5;
    const int wm = warp & 1;          // 2 warps along M (64 rows each)
    const int wn = warp >> 1;         // 4 warps along N (32 cols each)
    const int g  = lane >> 2;
    const int tg = lane & 3;

    const int bm = blockIdx.y * BM;
    const int bn = blockIdx.x * BN;

    const int ldr = tid >> 2;          // 0..63
    const int ldc = (tid & 3) * 4;     // 0,4,8,12

    const float* Ag0 = A + (size_t)(bm + ldr) * K + ldc;
    const float* Ag1 = A + (size_t)(bm + ldr + 64) * K + ldc;
    const float* Bg0 = B + (size_t)(bn + ldr) * K + ldc;
    const float* Bg1 = B + (size_t)(bn + ldr + 64) * K + ldc;

    auto load_stage = [&](int s, int ko) {
        float* As = sm + s * STAGE_FLOATS;
        float* Bs = As + BM * GST;
        cp_async16(As + ldr * GST + ldc,        Ag0 + ko);
        cp_async16(As + (ldr + 64) * GST + ldc, Ag1 + ko);
        cp_async16(Bs + ldr * GST + ldc,        Bg0 + ko);
        cp_async16(Bs + (ldr + 64) * GST + ldc, Bg1 + ko);
        cp_commit();
    };

    float acc[4][4][4];
#pragma unroll
    for (int mt = 0; mt < 4; mt++)
#pragma unroll
        for (int nt = 0; nt < 4; nt++)
#pragma unroll
            for (int i = 0; i < 4; i++) acc[mt][nt][i] = 0.f;

    const int nstages = K / BK;

    load_stage(0, 0);
    load_stage(1, BK);

    for (int it = 0; it < nstages; it++) {
        if (it + 1 < nstages) cp_wait<1>();
        else                  cp_wait<0>();
        __syncthreads();

        if (it + 2 < nstages)
            load_stage((it + 2) % NSTAGE, (it + 2) * BK);

        const float* Ab = sm + (it % NSTAGE) * STAGE_FLOATS;
        const float* Bb = Ab + BM * GST;

#pragma unroll
        for (int ks = 0; ks < BK; ks += 8) {
            uint32_t af[4][4], bf[4][2];
#pragma unroll
            for (int mt = 0; mt < 4; mt++) {
                const int m = wm * 64 + mt * 16;
                af[mt][0] = f2tf(Ab[(m + g) * GST + ks + tg]);
                af[mt][1] = f2tf(Ab[(m + g + 8) * GST + ks + tg]);
                af[mt][2] = f2tf(Ab[(m + g) * GST + ks + tg + 4]);
                af[mt][3] = f2tf(Ab[(m + g + 8) * GST + ks + tg + 4]);
            }
#pragma unroll
            for (int nt = 0; nt < 4; nt++) {
                const int n = wn * 32 + nt * 8;
                bf[nt][0] = f2tf(Bb[(n + g) * GST + ks + tg]);
                bf[nt][1] = f2tf(Bb[(n + g) * GST + ks + tg + 4]);
            }
#pragma unroll
            for (int mt = 0; mt < 4; mt++)
#pragma unroll
                for (int nt = 0; nt < 4; nt++)
                    mma_tf32(acc[mt][nt], af[mt], bf[nt]);
        }
    }

    const float qsc = 0.125f * 1.4426950408889634f;

#pragma unroll
    for (int mt = 0; mt < 4; mt++) {
        const int row0 = bm + wm * 64 + mt * 16 + g;
#pragma unroll
        for (int nt = 0; nt < 4; nt++) {
            const int col = bn + wn * 32 + nt * 8 + 2 * tg;
            float v0 = acc[mt][nt][0], v1 = acc[mt][nt][1];
            float v2 = acc[mt][nt][2], v3 = acc[mt][nt][3];
            if (QSCALE && col < DOUT) { v0 *= qsc; v1 *= qsc; v2 *= qsc; v3 *= qsc; }
            if (BIAS) {
                float b0 = bias[col], b1 = bias[col + 1];
                v0 += b0; v1 += b1; v2 += b0; v3 += b1;
            }
            if (ROUND) {
                v0 = tf32r(v0); v1 = tf32r(v1);
                v2 = tf32r(v2); v3 = tf32r(v3);
            }
            *(float2*)(C + (size_t)row0 * N + col) = make_float2(v0, v1);
            *(float2*)(C + (size_t)(row0 + 8) * N + col) = make_float2(v2, v3);
        }
    }
}

// ---------------------------------------------------------------------------
// Flash attention (causal), tf32 mma — R7 structure; exp2f -> ex2.approx
// (single MUFU EX2 independent of -use_fast_math).
// ---------------------------------------------------------------------------
#define KS_ST 68
#define VS_ST 72
#define FLASH_SMEM_BYTES ((2*64*KS_ST + 2*64*VS_ST + 128*KS_ST) * 4)

__global__ __launch_bounds__(256, 1) void flash_mma_kernel(
    const float* __restrict__ qkv, float* __restrict__ y)
{
    extern __shared__ float sm[];
    float (*Ks)[64][KS_ST] = (float(*)[64][KS_ST])sm;
    float (*Vs)[64][VS_ST] = (float(*)[64][VS_ST])(sm + 2 * 64 * KS_ST);
    float (*Ps)[KS_ST]     = (float(*)[KS_ST])(sm + 2 * 64 * KS_ST + 2 * 64 * VS_ST);

    const int qi = (int)gridDim.x - 1 - (int)blockIdx.x;  // heavy tiles first
    const int bh = blockIdx.y;
    const int b  = bh >> 4;
    const int h  = bh & 15;
    const int qbase = qi * 128;

    const float* base = qkv + (size_t)b * SEQ * QKV_COLS;
    const int hoff = h * HDIM;

    const int tid  = threadIdx.x;
    const int lane = tid & 31;
    const int warp = tid >> 5;
    const int g  = lane >> 2;
    const int tg = lane & 3;
    const int w16 = warp * 16;

    for (int i = tid; i < 128 * 16; i += 256) {
        int r  = i >> 4;
        int c4 = (i & 15) * 4;
        float4 v = *(const float4*)(base + (size_t)(qbase + r) * QKV_COLS + hoff + c4);
        *(float4*)&Ps[r][c4] = v;
    }
    __syncthreads();

    uint32_t aq[8][4];
#pragma unroll
    for (int ks = 0; ks < 8; ks++) {
        aq[ks][0] = __float_as_uint(Ps[w16 + g][ks * 8 + tg]);
        aq[ks][1] = __float_as_uint(Ps[w16 + g + 8][ks * 8 + tg]);
        aq[ks][2] = __float_as_uint(Ps[w16 + g][ks * 8 + tg + 4]);
        aq[ks][3] = __float_as_uint(Ps[w16 + g + 8][ks * 8 + tg + 4]);
    }
    __syncthreads();

    float O[8][4];
#pragma unroll
    for (int n = 0; n < 8; n++)
#pragma unroll
        for (int i = 0; i < 4; i++) O[n][i] = 0.f;
    float m0 = -1e30f, m1 = -1e30f, l0 = 0.f, l1 = 0.f;

    const int njt = 2 * (qi + 1);

    auto prefetch = [&](int jt, int buf) {
        const int jb = jt * 64;
        for (int i = tid; i < 64 * 16; i += 256) {
            int r  = i >> 4;
            int c4 = (i & 15) * 4;
            const float* rowp = base + (size_t)(jb + r) * QKV_COLS + hoff;
            cp_async16(&Ks[buf][r][c4], rowp + DOUT + c4);
            cp_async16(&Vs[buf][r][c4], rowp + 2 * DOUT + c4);
        }
        cp_commit();
    };

    prefetch(0, 0);

    for (int jt = 0; jt < njt; jt++) {
        const int buf = jt & 1;
        if (jt + 1 < njt) {
            prefetch(jt + 1, (jt + 1) & 1);
            cp_wait<1>();
        } else {
            cp_wait<0>();
        }
        __syncthreads();

        float S[8][4];
#pragma unroll
        for (int n = 0; n < 8; n++)
#pragma unroll
            for (int i = 0; i < 4; i++) S[n][i] = 0.f;

#pragma unroll
        for (int ks = 0; ks < 8; ks++) {
#pragma unroll
            for (int n = 0; n < 8; n++) {
                uint32_t kb[2];
                kb[0] = __float_as_uint(Ks[buf][n * 8 + g][ks * 8 + tg]);
                kb[1] = __float_as_uint(Ks[buf][n * 8 + g][ks * 8 + tg + 4]);
                mma_tf32(S[n], aq[ks], kb);
            }
        }

        if (jt >= 2 * qi) {
            const int r0 = qbase + w16 + g;
            const int r1 = r0 + 8;
            const int cb = jt * 64 + 2 * tg;
#pragma unroll
            for (int n = 0; n < 8; n++) {
                const int c0 = cb + n * 8;
                if (c0 > r0)     S[n][0] = -1e30f;
                if (c0 + 1 > r0) S[n][1] = -1e30f;
                if (c0 > r1)     S[n][2] = -1e30f;
                if (c0 + 1 > r1) S[n][3] = -1e30f;
            }
        }

        float rm0 = -1e30f, rm1 = -1e30f;
#pragma unroll
        for (int n = 0; n < 8; n++) {
            rm0 = fmaxf(rm0, fmaxf(S[n][0], S[n][1]));
            rm1 = fmaxf(rm1, fmaxf(S[n][2], S[n][3]));
        }
        rm0 = fmaxf(rm0, __shfl_xor_sync(0xffffffffu, rm0, 1));
        rm0 = fmaxf(rm0, __shfl_xor_sync(0xffffffffu, rm0, 2));
        rm1 = fmaxf(rm1, __shfl_xor_sync(0xffffffffu, rm1, 1));
        rm1 = fmaxf(rm1, __shfl_xor_sync(0xffffffffu, rm1, 2));

        const float mn0 = fmaxf(m0, rm0);
        const float mn1 = fmaxf(m1, rm1);
        const float corr0 = ex2(m0 - mn0);
        const float corr1 = ex2(m1 - mn1);
        m0 = mn0; m1 = mn1;

        float rs0 = 0.f, rs1 = 0.f;
#pragma unroll
        for (int n = 0; n < 8; n++) {
            float p0 = ex2(S[n][0] - mn0);
            float p1 = ex2(S[n][1] - mn0);
            float p2 = ex2(S[n][2] - mn1);
            float p3 = ex2(S[n][3] - mn1);
            rs0 += p0 + p1;
            rs1 += p2 + p3;
            O[n][0] *= corr0; O[n][1] *= corr0;
            O[n][2] *= corr1; O[n][3] *= corr1;
            *(float2*)&Ps[w16 + g][n * 8 + 2 * tg]     = make_float2(tf32r(p0), tf32r(p1));
            *(float2*)&Ps[w16 + g + 8][n * 8 + 2 * tg] = make_float2(tf32r(p2), tf32r(p3));
        }
        rs0 += __shfl_xor_sync(0xffffffffu, rs0, 1);
        rs0 += __shfl_xor_sync(0xffffffffu, rs0, 2);
        rs1 += __shfl_xor_sync(0xffffffffu, rs1, 1);
        rs1 += __shfl_xor_sync(0xffffffffu, rs1, 2);
        l0 = l0 * corr0 + rs0;
        l1 = l1 * corr1 + rs1;

        __syncwarp();

#pragma unroll
        for (int ks = 0; ks < 8; ks++) {
            uint32_t pa[4];
            pa[0] = __float_as_uint(Ps[w16 + g][ks * 8 + tg]);
            pa[1] = __float_as_uint(Ps[w16 + g + 8][ks * 8 + tg]);
            pa[2] = __float_as_uint(Ps[w16 + g][ks * 8 + tg + 4]);
            pa[3] = __float_as_uint(Ps[w16 + g + 8][ks * 8 + tg + 4]);
#pragma unroll
            for (int n = 0; n < 8; n++) {
                uint32_t vb[2];
                vb[0] = __float_as_uint(Vs[buf][ks * 8 + tg][n * 8 + g]);
                vb[1] = __float_as_uint(Vs[buf][ks * 8 + tg + 4][n * 8 + g]);
                mma_tf32(O[n], pa, vb);
            }
        }
        __syncthreads();
    }

    const float inv0 = rcp(l0);
    const float inv1 = rcp(l1);
    const int r0 = qbase + w16 + g;
    float* yr0 = y + (size_t)b * SEQ * DOUT + (size_t)r0 * DOUT + hoff;
    float* yr1 = yr0 + 8 * DOUT;
#pragma unroll
    for (int n = 0; n < 8; n++) {
        const int c = n * 8 + 2 * tg;
        *(float2*)(yr0 + c) = make_float2(tf32r(O[n][0] * inv0), tf32r(O[n][1] * inv0));
        *(float2*)(yr1 + c) = make_float2(tf32r(O[n][2] * inv1), tf32r(O[n][3] * inv1));
    }
}

// ---------------------------------------------------------------------------
extern "C" void kernel_launch(void* const* d_in, const int* in_sizes, int n_in,
                              void* d_out, int out_size)
{
    const float* x     = (const float*)d_in[0];
    const float* w_qkv = (const float*)d_in[1];
    const float* w_out = (const float*)d_in[2];
    const float* b_out = (const float*)d_in[3];
    float* out = (float*)d_out;

    float *qkv_ptr, *y_ptr;
    cudaGetSymbolAddress((void**)&qkv_ptr, g_qkv);
    cudaGetSymbolAddress((void**)&y_ptr, g_y);

    cudaFuncSetAttribute(gemm_tf32_nt<false, true, true>,
                         cudaFuncAttributeMaxDynamicSharedMemorySize,
                         GEMM_SMEM_BYTES);
    cudaFuncSetAttribute(gemm_tf32_nt<true, false, false>,
                         cudaFuncAttributeMaxDynamicSharedMemorySize,
                         GEMM_SMEM_BYTES);
    cudaFuncSetAttribute(flash_mma_kernel,
                         cudaFuncAttributeMaxDynamicSharedMemorySize,
                         FLASH_SMEM_BYTES);

    // 1) QKV projection (output tf32-rounded, Q pre-scaled by 0.125*log2e)
    gemm_tf32_nt<false, true, true>
        <<<dim3(QKV_COLS / BN, M_ROWS / BM), 256, GEMM_SMEM_BYTES>>>(
        x, w_qkv, nullptr, qkv_ptr, M_ROWS, QKV_COLS, DIN);

    // 2) Flash attention (y stored tf32-rounded)
    flash_mma_kernel<<<dim3(SEQ / 128, BATCH * NHEAD), 256, FLASH_SMEM_BYTES>>>(
        qkv_ptr, y_ptr);

    // 3) Output projection + bias (final fp32 output)
    gemm_tf32_nt<true, false, false>
        <<<dim3(DOUT / BN, M_ROWS / BM), 256, GEMM_SMEM_BYTES>>>(
        y_ptr, w_out, b_out, out, M_ROWS, DOUT, DOUT);
}